// round 4
// baseline (speedup 1.0000x reference)
#include <cuda_runtime.h>
#include <cstdint>
#include <math.h>

// Problem constants
#define T_    128
#define B_    64
#define TB_   8192      // T*B
#define N_    24        // joints
#define D_    256
#define H_    8
#define F_    32
#define HF_   256       // H*F
#define ND_   6144      // N*D  (input row stride)
#define OUTW_ 6144      // N*H*F
#define M1_   196608    // TB*N rows for KV gemm

// Scratch q,k,v in [tb][h][n][f] layout, fp32.
__device__ float g_q[TB_ * H_ * N_ * F_];
__device__ float g_k[TB_ * H_ * N_ * F_];
__device__ float g_v[TB_ * H_ * N_ * F_];
// tf32-bit copies of inputs (pre-rounded once)
__device__ uint32_t g_xt[TB_ * ND_];          // X
__device__ uint32_t g_wkt[HF_ * D_];          // Wk
__device__ uint32_t g_wvt[HF_ * D_];          // Wv
__device__ uint32_t g_wqt[H_ * N_ * F_ * D_]; // Wq

// ---------------------------------------------------------------------------
// helpers
// ---------------------------------------------------------------------------
__device__ __forceinline__ uint32_t smem_u32(const void* p) {
    uint32_t a;
    asm("{ .reg .u64 t; cvta.to.shared.u64 t, %1; cvt.u32.u64 %0, t; }"
        : "=r"(a) : "l"(p));
    return a;
}
__device__ __forceinline__ void cp_async16(uint32_t dst, const void* src) {
    asm volatile("cp.async.cg.shared.global [%0], [%1], 16;"
                 :: "r"(dst), "l"(src) : "memory");
}
__device__ __forceinline__ void cp_commit() {
    asm volatile("cp.async.commit_group;" ::: "memory");
}
__device__ __forceinline__ void cp_wait2() {
    asm volatile("cp.async.wait_group 2;" ::: "memory");
}
__device__ __forceinline__ void cp_wait1() {
    asm volatile("cp.async.wait_group 1;" ::: "memory");
}
__device__ __forceinline__ void cp_wait0() {
    asm volatile("cp.async.wait_group 0;" ::: "memory");
}
__device__ __forceinline__ uint32_t f2tf32(float f) {
    uint32_t u;
    asm("cvt.rna.tf32.f32 %0, %1;" : "=r"(u) : "f"(f));
    return u;
}
__device__ __forceinline__ void mma_tf32(float c[4], const uint32_t a[4],
                                         const uint32_t b[2]) {
    asm volatile(
        "mma.sync.aligned.m16n8k8.row.col.f32.tf32.tf32.f32 "
        "{%0,%1,%2,%3}, {%4,%5,%6,%7}, {%8,%9}, {%0,%1,%2,%3};"
        : "+f"(c[0]), "+f"(c[1]), "+f"(c[2]), "+f"(c[3])
        : "r"(a[0]), "r"(a[1]), "r"(a[2]), "r"(a[3]), "r"(b[0]), "r"(b[1]));
}

// Smem geometry: rows padded to 36 words (conflict-free frags, 16B aligned)
#define APAD   36
#define A_BYTES (128 * APAD * 4)        // 18432
#define B_BYTES (256 * APAD * 4)        // 36864
#define STAGE   (A_BYTES + B_BYTES)     // 55296
#define NSTG    3
#define GSMEM_BYTES (NSTG * STAGE + 1024)

// ---------------------------------------------------------------------------
// Pre-pass: fp32 -> tf32 bits (round-to-nearest), vectorized.
// ---------------------------------------------------------------------------
__global__ void conv_tf32_kernel(const float4* __restrict__ src,
                                 uint4* __restrict__ dst, int n4)
{
    for (int i = blockIdx.x * blockDim.x + threadIdx.x; i < n4;
         i += gridDim.x * blockDim.x) {
        float4 v = src[i];
        dst[i] = make_uint4(f2tf32(v.x), f2tf32(v.y), f2tf32(v.z), f2tf32(v.w));
    }
}

// ---------------------------------------------------------------------------
// GEMM inner chunk: pure LDS + HMMA (operands already tf32 bits in smem)
// ---------------------------------------------------------------------------
#define GEMM_COMPUTE_CHUNK(sA, sB)                                          \
    {                                                                       \
        _Pragma("unroll")                                                   \
        for (int ks = 0; ks < 4; ks++) {                                    \
            const int kk = ks * 8;                                          \
            uint32_t af[4][4];                                              \
            _Pragma("unroll")                                               \
            for (int mi = 0; mi < 4; mi++) {                                \
                const int r = mWarp + mi * 16 + gid;                        \
                af[mi][0] = sA[(r)     * APAD + kk + tig];                  \
                af[mi][1] = sA[(r + 8) * APAD + kk + tig];                  \
                af[mi][2] = sA[(r)     * APAD + kk + tig + 4];              \
                af[mi][3] = sA[(r + 8) * APAD + kk + tig + 4];              \
            }                                                               \
            uint32_t bf[8][2];                                              \
            _Pragma("unroll")                                               \
            for (int ni = 0; ni < 8; ni++) {                                \
                const int nn = nWarp + ni * 8 + gid;                        \
                bf[ni][0] = sB[nn * APAD + kk + tig];                       \
                bf[ni][1] = sB[nn * APAD + kk + tig + 4];                   \
            }                                                               \
            _Pragma("unroll")                                               \
            for (int mi = 0; mi < 4; mi++)                                  \
                _Pragma("unroll")                                           \
                for (int ni = 0; ni < 8; ni++)                              \
                    mma_tf32(c[mi][ni], af[mi], bf[ni]);                    \
        }                                                                   \
    }

#define PIPE_WAIT(ch)                                                       \
    { if ((ch) <= 5) cp_wait2(); else if ((ch) == 6) cp_wait1(); else cp_wait0(); }

// ---------------------------------------------------------------------------
// Kernel 1: K or V projection (blockIdx.z selects).
// ---------------------------------------------------------------------------
__global__ void __launch_bounds__(256, 1)
kv_mma_kernel(const float* __restrict__ bk, const float* __restrict__ bv)
{
    extern __shared__ char smem[];
    const uint32_t* W    = (blockIdx.z == 0) ? g_wkt : g_wvt;
    const float*    bias = (blockIdx.z == 0) ? bk : bv;
    float*          dst  = (blockIdx.z == 0) ? g_k : g_v;

    const int tid  = threadIdx.x;
    const int w    = tid >> 5, lane = tid & 31;
    const int gid  = lane >> 2, tig = lane & 3;
    const int mWarp = (w & 1) * 64;
    const int nWarp = (w >> 1) * 64;
    const int rowBase = blockIdx.x * 128;
    const uint32_t sb = smem_u32(smem);

    float* sbias = (float*)(smem + NSTG * STAGE);
    sbias[tid] = bias[tid];

    float c[4][8][4];
#pragma unroll
    for (int mi = 0; mi < 4; mi++)
#pragma unroll
        for (int ni = 0; ni < 8; ni++)
#pragma unroll
            for (int j = 0; j < 4; j++) c[mi][ni][j] = 0.f;

    auto load_stage = [&](int ch) {
        const int s = ch % NSTG;
        const int k0 = ch * 32;
        const uint32_t aBase = sb + s * STAGE;
        const uint32_t bBase = aBase + A_BYTES;
#pragma unroll
        for (int j = 0; j < 4; j++) {           // A: 128 x 32
            const int e = tid + 256 * j;
            const int r = e >> 3, c4 = e & 7;
            cp_async16(aBase + (uint32_t)(r * APAD + c4 * 4) * 4,
                       g_xt + (size_t)(rowBase + r) * D_ + k0 + c4 * 4);
        }
#pragma unroll
        for (int j = 0; j < 8; j++) {           // B: 256 x 32
            const int e = tid + 256 * j;
            const int o = e >> 3, c4 = e & 7;
            cp_async16(bBase + (uint32_t)(o * APAD + c4 * 4) * 4,
                       W + (size_t)o * D_ + k0 + c4 * 4);
        }
    };

    load_stage(0); cp_commit();
    load_stage(1); cp_commit();
    load_stage(2); cp_commit();

    for (int ch = 0; ch < 8; ch++) {
        PIPE_WAIT(ch);
        __syncthreads();
        const uint32_t* sA = (const uint32_t*)(smem + (ch % NSTG) * STAGE);
        const uint32_t* sB = (const uint32_t*)(smem + (ch % NSTG) * STAGE + A_BYTES);
        GEMM_COMPUTE_CHUNK(sA, sB);
        __syncthreads();
        if (ch + 3 < 8) { load_stage(ch + 3); cp_commit(); }
    }

#pragma unroll
    for (int mi = 0; mi < 4; mi++) {
        const int r0 = rowBase + mWarp + mi * 16 + gid;
#pragma unroll
        for (int rr = 0; rr < 2; rr++) {
            const int m = r0 + rr * 8;
            const int tb = m / N_, n = m - tb * N_;
#pragma unroll
            for (int ni = 0; ni < 8; ni++) {
                const int o = nWarp + ni * 8 + tig * 2;
                const int h = o >> 5, f = o & 31;
                float2 v;
                v.x = c[mi][ni][2 * rr + 0] + sbias[o];
                v.y = c[mi][ni][2 * rr + 1] + sbias[o + 1];
                *(float2*)&dst[(((size_t)tb * H_ + h) * N_ + n) * F_ + f] = v;
            }
        }
    }
}

// ---------------------------------------------------------------------------
// Kernel 2: Q projection for joint n = blockIdx.z.
// ---------------------------------------------------------------------------
__global__ void __launch_bounds__(256, 1)
q_mma_kernel(const float* __restrict__ bq)
{
    extern __shared__ char smem[];
    const int nJ = blockIdx.z;

    const int tid  = threadIdx.x;
    const int w    = tid >> 5, lane = tid & 31;
    const int gid  = lane >> 2, tig = lane & 3;
    const int mWarp = (w & 1) * 64;
    const int nWarp = (w >> 1) * 64;
    const int rowBase = blockIdx.x * 128;
    const uint32_t sb = smem_u32(smem);

    float* sbias = (float*)(smem + NSTG * STAGE);
    {
        const int h = tid >> 5, f = tid & 31;
        sbias[tid] = bq[(h * N_ + nJ) * F_ + f];
    }

    float c[4][8][4];
#pragma unroll
    for (int mi = 0; mi < 4; mi++)
#pragma unroll
        for (int ni = 0; ni < 8; ni++)
#pragma unroll
            for (int j = 0; j < 4; j++) c[mi][ni][j] = 0.f;

    auto load_stage = [&](int ch) {
        const int s = ch % NSTG;
        const int k0 = ch * 32;
        const uint32_t aBase = sb + s * STAGE;
        const uint32_t bBase = aBase + A_BYTES;
#pragma unroll
        for (int j = 0; j < 4; j++) {           // A: rows tb, stride ND_
            const int e = tid + 256 * j;
            const int r = e >> 3, c4 = e & 7;
            cp_async16(aBase + (uint32_t)(r * APAD + c4 * 4) * 4,
                       g_xt + (size_t)(rowBase + r) * ND_ + nJ * D_ + k0 + c4 * 4);
        }
#pragma unroll
        for (int j = 0; j < 8; j++) {           // B: Wq[h][nJ][f][:]
            const int e = tid + 256 * j;
            const int o = e >> 3, c4 = e & 7;
            const int h = o >> 5, f = o & 31;
            cp_async16(bBase + (uint32_t)(o * APAD + c4 * 4) * 4,
                       g_wqt + ((size_t)(h * N_ + nJ) * F_ + f) * D_ + k0 + c4 * 4);
        }
    };

    load_stage(0); cp_commit();
    load_stage(1); cp_commit();
    load_stage(2); cp_commit();

    for (int ch = 0; ch < 8; ch++) {
        PIPE_WAIT(ch);
        __syncthreads();
        const uint32_t* sA = (const uint32_t*)(smem + (ch % NSTG) * STAGE);
        const uint32_t* sB = (const uint32_t*)(smem + (ch % NSTG) * STAGE + A_BYTES);
        GEMM_COMPUTE_CHUNK(sA, sB);
        __syncthreads();
        if (ch + 3 < 8) { load_stage(ch + 3); cp_commit(); }
    }

#pragma unroll
    for (int mi = 0; mi < 4; mi++) {
        const int r0 = rowBase + mWarp + mi * 16 + gid;
#pragma unroll
        for (int rr = 0; rr < 2; rr++) {
            const int tb = r0 + rr * 8;
#pragma unroll
            for (int ni = 0; ni < 8; ni++) {
                const int o = nWarp + ni * 8 + tig * 2;
                const int h = o >> 5, f = o & 31;
                float2 v;
                v.x = c[mi][ni][2 * rr + 0] + sbias[o];
                v.y = c[mi][ni][2 * rr + 1] + sbias[o + 1];
                *(float2*)&g_q[(((size_t)tb * H_ + h) * N_ + nJ) * F_ + f] = v;
            }
        }
    }
}

// ---------------------------------------------------------------------------
// Kernel 3: attention. 1 warp per (tb, h). No per-n syncwarp (shfl broadcast).
// ---------------------------------------------------------------------------
__global__ __launch_bounds__(128)
void attn_kernel(float* __restrict__ out)
{
    __shared__ float sq[4][N_][33];
    __shared__ float sk[4][N_][33];
    __shared__ float sv[4][N_][33];

    const int tb   = blockIdx.x;
    const int w    = threadIdx.x >> 5;
    const int lane = threadIdx.x & 31;
    const int h    = blockIdx.y * 4 + w;

    const int base = ((tb * H_ + h) * N_) * F_;
    const float* qb = g_q + base;
    const float* kb = g_k + base;
    const float* vb = g_v + base;

    for (int i = lane; i < N_ * F_; i += 32) {
        const int r = i >> 5, cc = i & 31;
        sq[w][r][cc] = qb[i];
        sk[w][r][cc] = kb[i];
        sv[w][r][cc] = vb[i];
    }
    __syncwarp();

    const float scale = 0.17677669529663687f;  // 1/sqrt(32)

    for (int n = 0; n < N_; n++) {
        float s = -1e30f;
        if (lane < N_) {
            float acc = 0.f;
#pragma unroll
            for (int f = 0; f < F_; f++) acc += sq[w][n][f] * sk[w][lane][f];
            s = acc * scale;
        }
        float mx = s;
#pragma unroll
        for (int off = 16; off > 0; off >>= 1)
            mx = fmaxf(mx, __shfl_xor_sync(0xffffffffu, mx, off));
        float p = __expf(s - mx);
        if (lane >= N_) p = 0.f;
        float sum = p;
#pragma unroll
        for (int off = 16; off > 0; off >>= 1)
            sum += __shfl_xor_sync(0xffffffffu, sum, off);
        p *= __frcp_rn(sum);

        float acc = 0.f;
#pragma unroll
        for (int m = 0; m < N_; m++)
            acc += __shfl_sync(0xffffffffu, p, m) * sv[w][m][lane];
        out[tb * OUTW_ + (n * H_ + h) * F_ + lane] = acc;
    }
}

// ---------------------------------------------------------------------------
extern "C" void kernel_launch(void* const* d_in, const int* in_sizes, int n_in,
                              void* d_out, int out_size)
{
    const float* x  = (const float*)d_in[0];
    const float* Wk = (const float*)d_in[1];
    const float* bk = (const float*)d_in[2];
    const float* Wv = (const float*)d_in[3];
    const float* bv = (const float*)d_in[4];
    const float* Wq = (const float*)d_in[5];
    const float* bq = (const float*)d_in[6];
    float* out = (float*)d_out;

    cudaFuncSetAttribute(kv_mma_kernel,
                         cudaFuncAttributeMaxDynamicSharedMemorySize, GSMEM_BYTES);
    cudaFuncSetAttribute(q_mma_kernel,
                         cudaFuncAttributeMaxDynamicSharedMemorySize, GSMEM_BYTES);

    uint32_t* xt; uint32_t* wkt; uint32_t* wvt; uint32_t* wqt;
    cudaGetSymbolAddress((void**)&xt,  g_xt);
    cudaGetSymbolAddress((void**)&wkt, g_wkt);
    cudaGetSymbolAddress((void**)&wvt, g_wvt);
    cudaGetSymbolAddress((void**)&wqt, g_wqt);

    // Pre-pass: round inputs to tf32 bits once.
    conv_tf32_kernel<<<8192, 256>>>((const float4*)x,  (uint4*)xt,  TB_ * ND_ / 4);
    conv_tf32_kernel<<<64,   256>>>((const float4*)Wk, (uint4*)wkt, HF_ * D_ / 4);
    conv_tf32_kernel<<<64,   256>>>((const float4*)Wv, (uint4*)wvt, HF_ * D_ / 4);
    conv_tf32_kernel<<<1536, 256>>>((const float4*)Wq, (uint4*)wqt, H_ * N_ * F_ * D_ / 4);

    dim3 g1(M1_ / 128, 1, 2);
    kv_mma_kernel<<<g1, 256, GSMEM_BYTES>>>(bk, bv);

    dim3 g2(TB_ / 128, 1, N_);
    q_mma_kernel<<<g2, 256, GSMEM_BYTES>>>(bq);

    dim3 g3(TB_, 2);
    attn_kernel<<<g3, 128>>>(out);
}

// round 5
// speedup vs baseline: 1.4574x; 1.4574x over previous
#include <cuda_runtime.h>
#include <cstdint>
#include <math.h>

// Problem constants
#define T_    128
#define B_    64
#define TB_   8192      // T*B
#define N_    24        // joints
#define D_    256
#define H_    8
#define F_    32
#define HF_   256       // H*F
#define ND_   6144      // N*D
#define OUTW_ 6144      // N*H*F
#define M1_   196608    // TB*N rows for KV gemm

// Scratch q,k,v in [tb][h][n][f] layout, fp32.
__device__ float g_q[TB_ * H_ * N_ * F_];
__device__ float g_k[TB_ * H_ * N_ * F_];
__device__ float g_v[TB_ * H_ * N_ * F_];

// ---------------------------------------------------------------------------
// helpers
// ---------------------------------------------------------------------------
__device__ __forceinline__ uint32_t smem_u32(const void* p) {
    uint32_t a;
    asm("{ .reg .u64 t; cvta.to.shared.u64 t, %1; cvt.u32.u64 %0, t; }"
        : "=r"(a) : "l"(p));
    return a;
}
__device__ __forceinline__ void cp_async16(uint32_t dst, const void* src) {
    asm volatile("cp.async.cg.shared.global [%0], [%1], 16;"
                 :: "r"(dst), "l"(src) : "memory");
}
__device__ __forceinline__ void cp_commit() {
    asm volatile("cp.async.commit_group;" ::: "memory");
}
__device__ __forceinline__ void cp_wait1() {
    asm volatile("cp.async.wait_group 1;" ::: "memory");
}
__device__ __forceinline__ void cp_wait0() {
    asm volatile("cp.async.wait_group 0;" ::: "memory");
}
// fp32 (smem) -> tf32 reg with round-to-nearest
__device__ __forceinline__ uint32_t ld_tf32(const float* p) {
    uint32_t u;
    asm("cvt.rna.tf32.f32 %0, %1;" : "=r"(u) : "f"(*p));
    return u;
}
__device__ __forceinline__ void mma_tf32(float c[4], const uint32_t a[4],
                                         const uint32_t b[2]) {
    asm volatile(
        "mma.sync.aligned.m16n8k8.row.col.f32.tf32.tf32.f32 "
        "{%0,%1,%2,%3}, {%4,%5,%6,%7}, {%8,%9}, {%0,%1,%2,%3};"
        : "+f"(c[0]), "+f"(c[1]), "+f"(c[2]), "+f"(c[3])
        : "r"(a[0]), "r"(a[1]), "r"(a[2]), "r"(a[3]), "r"(b[0]), "r"(b[1]));
}

// Smem geometry: rows padded to 36 floats (conflict-free frags, 16B aligned)
#define APAD    36
#define AT_BYTES (128 * APAD * 4)       // 18432 (A tile 128 x 32)
#define BT_BYTES (128 * APAD * 4)       // 18432 (B tile 128 x 32)
#define STAGE   (AT_BYTES + BT_BYTES)   // 36864
#define GSMEM_BYTES (2 * STAGE + 512)   // 74240  -> 2 CTAs/SM

// ---------------------------------------------------------------------------
// GEMM inner chunk: CTA 128x128, warp tile 64x32, mma m16n8k8 tf32.
// mWarp = (w&1)*64, nWarp = (w>>1)*32.  c[4][4][4] = 64 accum regs.
// ---------------------------------------------------------------------------
#define GEMM_COMPUTE_CHUNK(sA, sB)                                          \
    {                                                                       \
        _Pragma("unroll")                                                   \
        for (int ks = 0; ks < 4; ks++) {                                    \
            const int kk = ks * 8;                                          \
            uint32_t af[4][4];                                              \
            _Pragma("unroll")                                               \
            for (int mi = 0; mi < 4; mi++) {                                \
                const int r = mWarp + mi * 16 + gid;                        \
                af[mi][0] = ld_tf32(sA + (r)     * APAD + kk + tig);        \
                af[mi][1] = ld_tf32(sA + (r + 8) * APAD + kk + tig);        \
                af[mi][2] = ld_tf32(sA + (r)     * APAD + kk + tig + 4);    \
                af[mi][3] = ld_tf32(sA + (r + 8) * APAD + kk + tig + 4);    \
            }                                                               \
            uint32_t bf[4][2];                                              \
            _Pragma("unroll")                                               \
            for (int ni = 0; ni < 4; ni++) {                                \
                const int nn = nWarp + ni * 8 + gid;                        \
                bf[ni][0] = ld_tf32(sB + nn * APAD + kk + tig);             \
                bf[ni][1] = ld_tf32(sB + nn * APAD + kk + tig + 4);         \
            }                                                               \
            _Pragma("unroll")                                               \
            for (int mi = 0; mi < 4; mi++)                                  \
                _Pragma("unroll")                                           \
                for (int ni = 0; ni < 4; ni++)                              \
                    mma_tf32(c[mi][ni], af[mi], bf[ni]);                    \
        }                                                                   \
    }

// ---------------------------------------------------------------------------
// Kernel 1: K or V projection. grid (1536, 2, 2): x=M tile, y=N tile, z=K/V.
// ---------------------------------------------------------------------------
__global__ void __launch_bounds__(256, 2)
kv_mma_kernel(const float* __restrict__ X,
              const float* __restrict__ Wk, const float* __restrict__ bk,
              const float* __restrict__ Wv, const float* __restrict__ bv)
{
    extern __shared__ char smem[];
    const float* W    = (blockIdx.z == 0) ? Wk : Wv;
    const float* bias = (blockIdx.z == 0) ? bk : bv;
    float* dst        = (blockIdx.z == 0) ? g_k : g_v;

    const int tid  = threadIdx.x;
    const int w    = tid >> 5, lane = tid & 31;
    const int gid  = lane >> 2, tig = lane & 3;
    const int mWarp = (w & 1) * 64;
    const int nWarp = (w >> 1) * 32;
    const int rowBase = blockIdx.x * 128;
    const int colBase = blockIdx.y * 128;
    const uint32_t sb = smem_u32(smem);

    float* sbias = (float*)(smem + 2 * STAGE);
    if (tid < 128) sbias[tid] = bias[colBase + tid];

    float c[4][4][4];
#pragma unroll
    for (int mi = 0; mi < 4; mi++)
#pragma unroll
        for (int ni = 0; ni < 4; ni++)
#pragma unroll
            for (int j = 0; j < 4; j++) c[mi][ni][j] = 0.f;

    auto load_stage = [&](int ch) {
        const int s = ch & 1;
        const int k0 = ch * 32;
        const uint32_t aBase = sb + s * STAGE;
        const uint32_t bBase = aBase + AT_BYTES;
#pragma unroll
        for (int j = 0; j < 4; j++) {
            const int e = tid + 256 * j;
            const int r = e >> 3, c4 = e & 7;
            cp_async16(aBase + (uint32_t)(r * APAD + c4 * 4) * 4,
                       X + (size_t)(rowBase + r) * D_ + k0 + c4 * 4);
            cp_async16(bBase + (uint32_t)(r * APAD + c4 * 4) * 4,
                       W + (size_t)(colBase + r) * D_ + k0 + c4 * 4);
        }
    };

    load_stage(0); cp_commit();
    load_stage(1); cp_commit();

    for (int ch = 0; ch < 8; ch++) {
        if (ch < 7) cp_wait1(); else cp_wait0();
        __syncthreads();
        const float* sA = (const float*)(smem + (ch & 1) * STAGE);
        const float* sB = (const float*)(smem + (ch & 1) * STAGE + AT_BYTES);
        GEMM_COMPUTE_CHUNK(sA, sB);
        __syncthreads();
        if (ch + 2 < 8) { load_stage(ch + 2); cp_commit(); }
    }

#pragma unroll
    for (int mi = 0; mi < 4; mi++) {
        const int r0 = rowBase + mWarp + mi * 16 + gid;
#pragma unroll
        for (int rr = 0; rr < 2; rr++) {
            const int m = r0 + rr * 8;
            const int tb = m / N_, n = m - tb * N_;
#pragma unroll
            for (int ni = 0; ni < 4; ni++) {
                const int oc = nWarp + ni * 8 + tig * 2;
                const int o = colBase + oc;
                const int h = o >> 5, f = o & 31;
                float2 v;
                v.x = c[mi][ni][2 * rr + 0] + sbias[oc];
                v.y = c[mi][ni][2 * rr + 1] + sbias[oc + 1];
                *(float2*)&dst[(((size_t)tb * H_ + h) * N_ + n) * F_ + f] = v;
            }
        }
    }
}

// ---------------------------------------------------------------------------
// Kernel 2: Q projection. grid (64, 2, 24): x=tb tile, y=N tile, z=joint.
// ---------------------------------------------------------------------------
__global__ void __launch_bounds__(256, 2)
q_mma_kernel(const float* __restrict__ X,
             const float* __restrict__ Wq, const float* __restrict__ bq)
{
    extern __shared__ char smem[];
    const int nJ = blockIdx.z;

    const int tid  = threadIdx.x;
    const int w    = tid >> 5, lane = tid & 31;
    const int gid  = lane >> 2, tig = lane & 3;
    const int mWarp = (w & 1) * 64;
    const int nWarp = (w >> 1) * 32;
    const int rowBase = blockIdx.x * 128;
    const int colBase = blockIdx.y * 128;
    const uint32_t sb = smem_u32(smem);

    float* sbias = (float*)(smem + 2 * STAGE);
    if (tid < 128) {
        const int o = colBase + tid;
        const int h = o >> 5, f = o & 31;
        sbias[tid] = bq[(h * N_ + nJ) * F_ + f];
    }

    float c[4][4][4];
#pragma unroll
    for (int mi = 0; mi < 4; mi++)
#pragma unroll
        for (int ni = 0; ni < 4; ni++)
#pragma unroll
            for (int j = 0; j < 4; j++) c[mi][ni][j] = 0.f;

    auto load_stage = [&](int ch) {
        const int s = ch & 1;
        const int k0 = ch * 32;
        const uint32_t aBase = sb + s * STAGE;
        const uint32_t bBase = aBase + AT_BYTES;
#pragma unroll
        for (int j = 0; j < 4; j++) {
            const int e = tid + 256 * j;
            const int r = e >> 3, c4 = e & 7;
            cp_async16(aBase + (uint32_t)(r * APAD + c4 * 4) * 4,
                       X + (size_t)(rowBase + r) * ND_ + nJ * D_ + k0 + c4 * 4);
            const int o = colBase + r;
            const int h = o >> 5, f = o & 31;
            cp_async16(bBase + (uint32_t)(r * APAD + c4 * 4) * 4,
                       Wq + ((size_t)(h * N_ + nJ) * F_ + f) * D_ + k0 + c4 * 4);
        }
    };

    load_stage(0); cp_commit();
    load_stage(1); cp_commit();

    for (int ch = 0; ch < 8; ch++) {
        if (ch < 7) cp_wait1(); else cp_wait0();
        __syncthreads();
        const float* sA = (const float*)(smem + (ch & 1) * STAGE);
        const float* sB = (const float*)(smem + (ch & 1) * STAGE + AT_BYTES);
        GEMM_COMPUTE_CHUNK(sA, sB);
        __syncthreads();
        if (ch + 2 < 8) { load_stage(ch + 2); cp_commit(); }
    }

#pragma unroll
    for (int mi = 0; mi < 4; mi++) {
        const int r0 = rowBase + mWarp + mi * 16 + gid;
#pragma unroll
        for (int rr = 0; rr < 2; rr++) {
            const int tb = r0 + rr * 8;
#pragma unroll
            for (int ni = 0; ni < 4; ni++) {
                const int oc = nWarp + ni * 8 + tig * 2;
                const int o = colBase + oc;
                const int h = o >> 5, f = o & 31;
                float2 v;
                v.x = c[mi][ni][2 * rr + 0] + sbias[oc];
                v.y = c[mi][ni][2 * rr + 1] + sbias[oc + 1];
                *(float2*)&g_q[(((size_t)tb * H_ + h) * N_ + nJ) * F_ + f] = v;
            }
        }
    }
}

// ---------------------------------------------------------------------------
// Kernel 3: attention, lane-owns-row. 1 warp per (tb, h), grid (TB, 2) x 128.
//   Lane n (<24) keeps its 24 scores in registers -> no shfl reduction chains.
// ---------------------------------------------------------------------------
__global__ __launch_bounds__(128)
void attn_kernel(float* __restrict__ out)
{
    __shared__ float  sq[4][N_][33];     // q rows (scalar, conflict-free) ; reused as sout
    __shared__ float4 sk4[4][N_][9];     // k rows as float4 (broadcast reads)
    __shared__ float4 sv4[4][N_][9];     // v rows as float4

    const int tb   = blockIdx.x;
    const int w    = threadIdx.x >> 5;
    const int lane = threadIdx.x & 31;
    const int h    = blockIdx.y * 4 + w;

    const size_t base = ((size_t)(tb * H_ + h)) * N_ * F_;
    const float* qb = g_q + base;
    const float* kb = g_k + base;
    const float* vb = g_v + base;

    // load q scalar; k,v as float4
    for (int i = lane; i < N_ * F_; i += 32)
        sq[w][i >> 5][i & 31] = qb[i];
    for (int i = lane; i < N_ * 8; i += 32) {
        const int r = i >> 3, c = i & 7;
        sk4[w][r][c] = ((const float4*)kb)[i];
        sv4[w][r][c] = ((const float4*)vb)[i];
    }
    __syncwarp();

    const float scale = 0.17677669529663687f;  // 1/sqrt(32)

    float p[N_];
    if (lane < N_) {
        // q row into registers
        float q[F_];
#pragma unroll
        for (int f = 0; f < F_; f++) q[f] = sq[w][lane][f];

        // scores: s[m] = q . k[m]
#pragma unroll
        for (int m = 0; m < N_; m++) {
            float acc = 0.f;
#pragma unroll
            for (int c = 0; c < 8; c++) {
                float4 k4 = sk4[w][m][c];
                acc += q[4 * c + 0] * k4.x + q[4 * c + 1] * k4.y
                     + q[4 * c + 2] * k4.z + q[4 * c + 3] * k4.w;
            }
            p[m] = acc * scale;
        }
        // softmax in registers
        float mx = p[0];
#pragma unroll
        for (int m = 1; m < N_; m++) mx = fmaxf(mx, p[m]);
        float sum = 0.f;
#pragma unroll
        for (int m = 0; m < N_; m++) { p[m] = __expf(p[m] - mx); sum += p[m]; }
        const float inv = __frcp_rn(sum);
#pragma unroll
        for (int m = 0; m < N_; m++) p[m] *= inv;
    }
    __syncwarp();   // q reads done; sq becomes sout

    if (lane < N_) {
#pragma unroll
        for (int c = 0; c < 8; c++) {
            float4 acc = make_float4(0.f, 0.f, 0.f, 0.f);
#pragma unroll
            for (int m = 0; m < N_; m++) {
                float4 v4 = sv4[w][m][c];
                acc.x += p[m] * v4.x;  acc.y += p[m] * v4.y;
                acc.z += p[m] * v4.z;  acc.w += p[m] * v4.w;
            }
            sq[w][lane][4 * c + 0] = acc.x;
            sq[w][lane][4 * c + 1] = acc.y;
            sq[w][lane][4 * c + 2] = acc.z;
            sq[w][lane][4 * c + 3] = acc.w;
        }
    }
    __syncwarp();

    // coalesced store: row n -> out[tb][(n*H+h)*F + f]
    for (int i = lane; i < N_ * F_; i += 32) {
        const int n = i >> 5, f = i & 31;
        out[(size_t)tb * OUTW_ + (n * H_ + h) * F_ + f] = sq[w][n][f];
    }
}

// ---------------------------------------------------------------------------
extern "C" void kernel_launch(void* const* d_in, const int* in_sizes, int n_in,
                              void* d_out, int out_size)
{
    const float* x  = (const float*)d_in[0];
    const float* Wk = (const float*)d_in[1];
    const float* bk = (const float*)d_in[2];
    const float* Wv = (const float*)d_in[3];
    const float* bv = (const float*)d_in[4];
    const float* Wq = (const float*)d_in[5];
    const float* bq = (const float*)d_in[6];
    float* out = (float*)d_out;

    cudaFuncSetAttribute(kv_mma_kernel,
                         cudaFuncAttributeMaxDynamicSharedMemorySize, GSMEM_BYTES);
    cudaFuncSetAttribute(q_mma_kernel,
                         cudaFuncAttributeMaxDynamicSharedMemorySize, GSMEM_BYTES);

    dim3 g1(M1_ / 128, 2, 2);
    kv_mma_kernel<<<g1, 256, GSMEM_BYTES>>>(x, Wk, bk, Wv, bv);

    dim3 g2(TB_ / 128, 2, N_);
    q_mma_kernel<<<g2, 256, GSMEM_BYTES>>>(x, Wq, bq);

    dim3 g3(TB_, 2);
    attn_kernel<<<g3, 128>>>(out);
}